// round 5
// baseline (speedup 1.0000x reference)
#include <cuda_runtime.h>

// FoldLayer: overlap-add fold (col2im), K=3, S=2, D=1, pad=1 ('same'), cropped.
// patches: (B=16, GH=64, GW=64, K*K*C=1152) fp32, kernel-major slots (i*3+j)*C+c
// out:     (B=16, 128, 128, C=128) fp32
//
// Gather formulation: out[b, oy, ox, c] = sum over (y,i): 2y+i == oy+1, 0<=y<64,
//                                          and (x,j): 2x+j == ox+1, 0<=x<64
//                     of patches[b, y, x, (i*3+j)*128 + c]
// Each contributing input element is read exactly once -> bandwidth-optimal.

#define B_   16
#define GH_  64
#define GW_  64
#define C4_  32          // C=128 floats = 32 float4
#define OUTHW 128
#define NSLOT 9

__global__ __launch_bounds__(256)
void fold_gather_kernel(const float4* __restrict__ p, float4* __restrict__ out) {
    const int warp = (blockIdx.x * blockDim.x + threadIdx.x) >> 5;
    const int lane = threadIdx.x & 31;

    // total warps == total output pixels == B*128*128 == 262144 (exact grid)
    const int ox  = warp & (OUTHW - 1);
    const int t   = warp >> 7;
    const int oy  = t & (OUTHW - 1);
    const int b   = t >> 7;

    const int yc = oy + 1;   // canvas coords (pad=1)
    const int xc = ox + 1;

    // y contributions: (y, i) with 2y + i == yc
    int ys[2], is[2], ny = 0;
    if (yc & 1) {
        ys[0] = yc >> 1; is[0] = 1; ny = 1;        // i=1, y=(yc-1)/2, always valid
    } else {
        const int y0 = yc >> 1;                     // i=0
        if (y0 < GH_) { ys[ny] = y0; is[ny] = 0; ny++; }
        ys[ny] = (yc - 2) >> 1; is[ny] = 2; ny++;   // i=2, y>=0 since yc>=2
    }

    // x contributions: (x, j) with 2x + j == xc
    int xs[2], js[2], nx = 0;
    if (xc & 1) {
        xs[0] = xc >> 1; js[0] = 1; nx = 1;
    } else {
        const int x0 = xc >> 1;
        if (x0 < GW_) { xs[nx] = x0; js[nx] = 0; nx++; }
        xs[nx] = (xc - 2) >> 1; js[nx] = 2; nx++;
    }

    float4 acc = make_float4(0.f, 0.f, 0.f, 0.f);

    #pragma unroll 2
    for (int a = 0; a < ny; a++) {
        const int rowBase = (b * GH_ + ys[a]) * GW_;   // patch row base
        const int iK = is[a] * 3;
        #pragma unroll 2
        for (int q = 0; q < nx; q++) {
            // float4 index into patches: (((b*GH+y)*GW + x)*9 + slot)*32 + lane
            const int idx = ((rowBase + xs[q]) * NSLOT + (iK + js[q])) * C4_ + lane;
            const float4 v = __ldg(&p[idx]);
            acc.x += v.x; acc.y += v.y; acc.z += v.z; acc.w += v.w;
        }
    }

    out[warp * C4_ + lane] = acc;
}

extern "C" void kernel_launch(void* const* d_in, const int* in_sizes, int n_in,
                              void* d_out, int out_size) {
    (void)in_sizes; (void)n_in; (void)out_size;
    const float4* p = (const float4*)d_in[0];
    float4* out = (float4*)d_out;

    // one warp per output pixel: 16*128*128 = 262144 warps; 8 warps/block
    const int total_warps = B_ * OUTHW * OUTHW;
    const int threads = 256;
    const int blocks = (total_warps * 32) / threads;   // 32768
    fold_gather_kernel<<<blocks, threads>>>(p, out);
}

// round 8
// speedup vs baseline: 1.2121x; 1.2121x over previous
#include <cuda_runtime.h>

// FoldLayer fold (col2im), K=3, S=2, D=1, pad=1, cropped.
// patches: (B=16, GH=64, GW=64, 9*128) fp32, slot-major (i*3+j)*128+c
// out:     (B=16, 128, 128, 128) fp32
//
// Quad-gather: one warp per 2x2 output quad. The quad (2Y..2Y+1, 2X..2X+1)
// is fed by exactly the 9 slots of patches (Y,X),(Y,X+1),(Y+1,X),(Y+1,X+1):
//   out(2Y,  2X)   = P(Y,X)[s4]
//   out(2Y,  2X+1) = P(Y,X)[s5] + P(Y,X+1)[s3]
//   out(2Y+1,2X)   = P(Y,X)[s7] + P(Y+1,X)[s1]
//   out(2Y+1,2X+1) = P(Y,X)[s8] + P(Y,X+1)[s6] + P(Y+1,X)[s2] + P(Y+1,X+1)[s0]
// with X+1 / Y+1 terms dropped at the X=63 / Y=63 edge (warp-uniform predicate).
// One address computation amortized over 9 loads + 4 stores; all offsets are
// compile-time constants. Every load/store is a coalesced 512B warp transaction.

#define GH_  64
#define GW_  64
#define C4_  32              // 128 floats = 32 float4 per lane-vector
#define PSTRIDE (9 * C4_)    // float4s per patch = 288

__device__ __forceinline__ void acc4(float4& a, const float4 v) {
    a.x += v.x; a.y += v.y; a.z += v.z; a.w += v.w;
}

__global__ __launch_bounds__(256)
void fold_quad_kernel(const float4* __restrict__ p, float4* __restrict__ out) {
    const int warp = (blockIdx.x * blockDim.x + threadIdx.x) >> 5;
    const int lane = threadIdx.x & 31;

    // 16*64*64 = 65536 warps, one per quad
    const int X = warp & 63;
    const int Y = (warp >> 6) & 63;
    const int b = warp >> 12;

    const bool okX = (X < 63);
    const bool okY = (Y < 63);

    // float4 base of patch (Y,X), this lane's channel chunk
    const int pb  = ((b * GH_ + Y) * GW_ + X) * PSTRIDE + lane;
    const int p01 = pb + PSTRIDE;              // patch (Y, X+1)
    const int p10 = pb + GW_ * PSTRIDE;        // patch (Y+1, X)
    const int p11 = p10 + PSTRIDE;             // patch (Y+1, X+1)

    const float4 z = make_float4(0.f, 0.f, 0.f, 0.f);

    // Issue all 9 loads up front for maximal MLP (guarded ones predicated).
    const float4 v4 = __ldg(&p[pb  + 4 * C4_]);
    const float4 v5 = __ldg(&p[pb  + 5 * C4_]);
    const float4 v7 = __ldg(&p[pb  + 7 * C4_]);
    const float4 v8 = __ldg(&p[pb  + 8 * C4_]);
    const float4 v3 = okX ? __ldg(&p[p01 + 3 * C4_]) : z;
    const float4 v6 = okX ? __ldg(&p[p01 + 6 * C4_]) : z;
    const float4 v1 = okY ? __ldg(&p[p10 + 1 * C4_]) : z;
    const float4 v2 = okY ? __ldg(&p[p10 + 2 * C4_]) : z;
    const float4 v0 = (okX && okY) ? __ldg(&p[p11]) : z;

    float4 a00 = v4;
    float4 a01 = v5;  acc4(a01, v3);
    float4 a10 = v7;  acc4(a10, v1);
    float4 a11 = v8;  acc4(a11, v6);  acc4(a11, v2);  acc4(a11, v0);

    // output base: pixel (2Y, 2X)
    const int ob = ((b * 128 + 2 * Y) * 128 + 2 * X) * C4_ + lane;
    out[ob]               = a00;
    out[ob + C4_]         = a01;
    out[ob + 128 * C4_]   = a10;
    out[ob + 129 * C4_]   = a11;
}

extern "C" void kernel_launch(void* const* d_in, const int* in_sizes, int n_in,
                              void* d_out, int out_size) {
    (void)in_sizes; (void)n_in; (void)out_size;
    const float4* p = (const float4*)d_in[0];
    float4* out = (float4*)d_out;

    // 65536 warps total, 8 warps (256 threads) per block -> 8192 blocks
    fold_quad_kernel<<<8192, 256>>>(p, out);
}